// round 1
// baseline (speedup 1.0000x reference)
#include <cuda_runtime.h>
#include <cuda_bf16.h>
#include <cstdint>

#define B_SZ 8
#define SEQ_L 2048
#define DM 256
#define DI 512
#define DS 16
#define DTR 16
#define DC 4
#define NL 3
#define BL (B_SZ * SEQ_L)   // 16384

// ---------------- scratch (device globals: no allocs allowed) ----------------
__device__ float g_hn[(size_t)BL * DM];        // layernorm output
__device__ float g_xz[(size_t)BL * 2 * DI];    // in_proj output: [:,0:512]=u_raw, [:,512:1024]=z
__device__ float g_u [(size_t)BL * DI];        // conv+silu output
__device__ float g_dbc[(size_t)BL * 48];       // x_proj output: [dt16 | B16 | C16]
__device__ float g_dt[(size_t)BL * DI];        // softplus dt
__device__ float g_y [(size_t)BL * DI];        // scan (+gating) output

// ---------------- copy x -> out ----------------
__global__ void copy_f32(const float* __restrict__ in, float* __restrict__ out, int n) {
    int i = blockIdx.x * blockDim.x + threadIdx.x;
    if (i < n) out[i] = in[i];
}

// ---------------- layernorm: one block (256 thr) per row ----------------
__global__ void layernorm_k(const float* __restrict__ h, const float* __restrict__ g,
                            const float* __restrict__ b, float* __restrict__ o) {
    __shared__ float red[16];
    __shared__ float smu, srv;
    int row = blockIdx.x;
    int tid = threadIdx.x;
    float v = h[(size_t)row * DM + tid];
    float s = v, s2 = v * v;
    #pragma unroll
    for (int off = 16; off; off >>= 1) {
        s  += __shfl_xor_sync(0xffffffffu, s,  off);
        s2 += __shfl_xor_sync(0xffffffffu, s2, off);
    }
    int w = tid >> 5;
    if ((tid & 31) == 0) { red[w] = s; red[8 + w] = s2; }
    __syncthreads();
    if (tid == 0) {
        float S = 0.f, S2 = 0.f;
        #pragma unroll
        for (int i = 0; i < 8; i++) { S += red[i]; S2 += red[8 + i]; }
        float mu = S * (1.f / DM);
        smu = mu;
        srv = rsqrtf(S2 * (1.f / DM) - mu * mu + 1e-5f);
    }
    __syncthreads();
    o[(size_t)row * DM + tid] = (v - smu) * srv * g[tid] + b[tid];
}

// ---------------- generic SGEMM: C[M,N] = A[M,K] * W[N,K]^T ----------------
// EPI 0: store; EPI 1: softplus(acc + bias[n]); EPI 2: accumulate into C.
template <int EPI>
__global__ __launch_bounds__(256)
void sgemm_nt(const float* __restrict__ A, int lda,
              const float* __restrict__ W,
              const float* __restrict__ bias,
              float* __restrict__ C, int ldc,
              int M, int N, int K) {
    const int BM = 64, BN = 64, BK = 16;
    __shared__ float As[BK][BM + 4];
    __shared__ float Bs[BK][BN + 4];
    int tid = threadIdx.x;
    int m0 = blockIdx.x * BM;
    int n0 = blockIdx.y * BN;
    int tx = tid & 15, ty = tid >> 4;
    float acc[4][4] = {};
    int l_r = tid >> 2;          // 0..63 : row within tile
    int l_k = (tid & 3) * 4;     // 0,4,8,12

    for (int k0 = 0; k0 < K; k0 += BK) {
        // A tile
        float4 av = *(const float4*)(A + (size_t)(m0 + l_r) * lda + k0 + l_k);
        As[l_k + 0][l_r] = av.x;
        As[l_k + 1][l_r] = av.y;
        As[l_k + 2][l_r] = av.z;
        As[l_k + 3][l_r] = av.w;
        // W tile (guard N)
        int bn = n0 + l_r;
        float4 bv = make_float4(0.f, 0.f, 0.f, 0.f);
        if (bn < N) bv = *(const float4*)(W + (size_t)bn * K + k0 + l_k);
        Bs[l_k + 0][l_r] = bv.x;
        Bs[l_k + 1][l_r] = bv.y;
        Bs[l_k + 2][l_r] = bv.z;
        Bs[l_k + 3][l_r] = bv.w;
        __syncthreads();
        #pragma unroll
        for (int k = 0; k < BK; ++k) {
            float4 ar = *(const float4*)&As[k][ty * 4];
            float4 br = *(const float4*)&Bs[k][tx * 4];
            float a[4] = {ar.x, ar.y, ar.z, ar.w};
            float b[4] = {br.x, br.y, br.z, br.w};
            #pragma unroll
            for (int i = 0; i < 4; i++)
                #pragma unroll
                for (int j = 0; j < 4; j++)
                    acc[i][j] += a[i] * b[j];
        }
        __syncthreads();
    }

    #pragma unroll
    for (int i = 0; i < 4; i++) {
        int m = m0 + ty * 4 + i;
        #pragma unroll
        for (int j = 0; j < 4; j++) {
            int n = n0 + tx * 4 + j;
            if (n < N) {
                float v = acc[i][j];
                if (EPI == 1) {
                    v += bias[n];
                    // softplus, numerically safe
                    v = fmaxf(v, 0.f) + log1pf(__expf(-fabsf(v)));
                }
                if (EPI == 2) v += C[(size_t)m * ldc + n];
                C[(size_t)m * ldc + n] = v;
            }
        }
    }
}

// ---------------- causal depthwise conv1d + SiLU ----------------
__global__ void conv_silu_k(const float* __restrict__ xz, const float* __restrict__ w,
                            const float* __restrict__ bias, float* __restrict__ u) {
    int idx = blockIdx.x * blockDim.x + threadIdx.x;
    if (idx >= BL * DI) return;
    int d   = idx & (DI - 1);
    int row = idx >> 9;          // b*L + t
    int t   = row & (SEQ_L - 1);
    float acc = bias[d];
    #pragma unroll
    for (int k = 0; k < DC; ++k) {
        int tt = t - (DC - 1) + k;
        if (tt >= 0) acc += w[d * DC + k] * xz[(size_t)(row - (DC - 1) + k) * (2 * DI) + d];
    }
    u[idx] = acc / (1.f + __expf(-acc));   // SiLU
}

// ---------------- selective scan (fused gating epilogue) ----------------
// grid = B_SZ * 32 blocks of 256 threads; block handles batch b, channels d0..d0+15.
// thread = (channel c = tid>>4, state s = tid&15). 16-lane shfl reduce over states.
#define TCH 64
__global__ __launch_bounds__(256)
void scan_k(const float* __restrict__ dt, const float* __restrict__ u,
            const float* __restrict__ dbc, const float* __restrict__ xz,
            const float* __restrict__ A_log, const float* __restrict__ Dp,
            float* __restrict__ y) {
    __shared__ float s_dt[TCH][16];
    __shared__ float s_u [TCH][16];
    __shared__ float s_b [TCH][16];
    __shared__ float s_c [TCH][16];
    __shared__ float s_z [TCH][16];

    int b  = blockIdx.x >> 5;
    int d0 = (blockIdx.x & 31) * 16;
    int c  = threadIdx.x >> 4;
    int s  = threadIdx.x & 15;
    int d  = d0 + c;

    float Acoef = -__expf(A_log[d * DS + s]);
    float Dv = Dp[d];
    float h = 0.f;

    size_t base = (size_t)b * SEQ_L;
    for (int t0 = 0; t0 < SEQ_L; t0 += TCH) {
        __syncthreads();
        for (int j = threadIdx.x; j < TCH * 16; j += 256) {
            int r = j >> 4, cc = j & 15;
            size_t row = base + t0 + r;
            s_dt[r][cc] = dt[row * DI + d0 + cc];
            s_u [r][cc] = u [row * DI + d0 + cc];
            s_z [r][cc] = xz[row * (2 * DI) + DI + d0 + cc];
            s_b [r][cc] = dbc[row * 48 + 16 + cc];
            s_c [r][cc] = dbc[row * 48 + 32 + cc];
        }
        __syncthreads();
        #pragma unroll 4
        for (int tt = 0; tt < TCH; ++tt) {
            float dtv = s_dt[tt][c];
            float uv  = s_u[tt][c];
            float dA  = __expf(dtv * Acoef);
            h = h * dA + dtv * uv * s_b[tt][s];
            float yp = h * s_c[tt][s];
            yp += __shfl_xor_sync(0xffffffffu, yp, 8);
            yp += __shfl_xor_sync(0xffffffffu, yp, 4);
            yp += __shfl_xor_sync(0xffffffffu, yp, 2);
            yp += __shfl_xor_sync(0xffffffffu, yp, 1);
            if (s == 0) {
                float zv = s_z[tt][c];
                float sz = zv / (1.f + __expf(-zv));
                y[(base + t0 + tt) * DI + d] = (yp + uv * Dv) * sz;
            }
        }
    }
}

// ---------------- host launcher ----------------
extern "C" void kernel_launch(void* const* d_in, const int* in_sizes, int n_in,
                              void* d_out, int out_size) {
    const float* x        = (const float*)d_in[0];
    const float* ln_g     = (const float*)d_in[1];
    const float* ln_b     = (const float*)d_in[2];
    const float* in_w     = (const float*)d_in[3];
    const float* conv_w   = (const float*)d_in[4];
    const float* conv_b   = (const float*)d_in[5];
    const float* xproj_w  = (const float*)d_in[6];
    const float* dtproj_w = (const float*)d_in[7];
    const float* dtproj_b = (const float*)d_in[8];
    const float* A_log    = (const float*)d_in[9];
    const float* Dp       = (const float*)d_in[10];
    const float* out_w    = (const float*)d_in[11];
    float* out = (float*)d_out;

    float *hn, *xz, *u, *dbc, *dt, *y;
    cudaGetSymbolAddress((void**)&hn,  g_hn);
    cudaGetSymbolAddress((void**)&xz,  g_xz);
    cudaGetSymbolAddress((void**)&u,   g_u);
    cudaGetSymbolAddress((void**)&dbc, g_dbc);
    cudaGetSymbolAddress((void**)&dt,  g_dt);
    cudaGetSymbolAddress((void**)&y,   g_y);

    const int n_out = BL * DM;
    copy_f32<<<(n_out + 255) / 256, 256>>>(x, out, n_out);

    for (int i = 0; i < NL; ++i) {
        // 1. layernorm
        layernorm_k<<<BL, 256>>>(out, ln_g, ln_b, hn);
        // 2. in_proj: xz[BL,1024] = hn[BL,256] @ in_w[i][1024,256]^T
        sgemm_nt<0><<<dim3(BL / 64, 1024 / 64), 256>>>(
            hn, DM, in_w + (size_t)i * 2 * DI * DM, nullptr, xz, 2 * DI, BL, 2 * DI, DM);
        // 3. conv + silu -> u
        conv_silu_k<<<(BL * DI + 255) / 256, 256>>>(
            xz, conv_w + (size_t)i * DI * DC, conv_b + (size_t)i * DI, u);
        // 4. x_proj: dbc[BL,48] = u @ xproj_w[i][48,512]^T
        sgemm_nt<0><<<dim3(BL / 64, 1), 256>>>(
            u, DI, xproj_w + (size_t)i * 48 * DI, nullptr, dbc, 48, BL, 48, DI);
        // 5. dt: softplus(dbc[:, :16] @ dtproj_w[i][512,16]^T + b)
        sgemm_nt<1><<<dim3(BL / 64, DI / 64), 256>>>(
            dbc, 48, dtproj_w + (size_t)i * DI * DTR, dtproj_b + (size_t)i * DI,
            dt, DI, BL, DI, DTR);
        // 6. selective scan + u*Dp + silu(z) gating -> y
        scan_k<<<B_SZ * 32, 256>>>(dt, u, dbc, xz,
                                   A_log + (size_t)i * DI * DS, Dp + (size_t)i * DI, y);
        // 7. out_proj with residual accumulate: out += y @ out_w[i][256,512]^T
        sgemm_nt<2><<<dim3(BL / 64, DM / 64), 256>>>(
            y, DI, out_w + (size_t)i * DM * DI, nullptr, out, DM, BL, DM, DI);
    }
}

// round 3
// speedup vs baseline: 1.5434x; 1.5434x over previous
#include <cuda_runtime.h>
#include <cuda_bf16.h>
#include <cstdint>

#define B_SZ 8
#define SEQ_L 2048
#define DM 256
#define DI 512
#define DS 16
#define DTR 16
#define DC 4
#define NL 3
#define BL (B_SZ * SEQ_L)   // 16384

#define SW128(o) ((o) ^ ((((o) >> 3)) & 0x70))

// ---------------- scratch (device globals) ----------------
__device__ __align__(1024) __nv_bfloat16 g_hn_b[(size_t)BL * DM];
__device__ __align__(1024) float         g_xz  [(size_t)BL * 2 * DI];
__device__ __align__(1024) float         g_u   [(size_t)BL * DI];
__device__ __align__(1024) __nv_bfloat16 g_u_b [(size_t)BL * DI];
__device__ __align__(1024) float         g_dbc [(size_t)BL * 48];
__device__ __align__(1024) float         g_dt  [(size_t)BL * DI];
__device__ __align__(1024) __nv_bfloat16 g_y_b [(size_t)BL * DI];
__device__ __align__(1024) __nv_bfloat16 g_win_b [(size_t)NL * 2 * DI * DM];
__device__ __align__(1024) __nv_bfloat16 g_wx_b  [(size_t)NL * 64 * DI];   // padded 48->64
__device__ __align__(1024) __nv_bfloat16 g_wout_b[(size_t)NL * DM * DI];

// ---------------- helpers ----------------
__device__ __forceinline__ uint32_t smem_u32(const void* p) {
    uint32_t a;
    asm("{ .reg .u64 t; cvta.to.shared.u64 t, %1; cvt.u32.u64 %0, t; }" : "=r"(a) : "l"(p));
    return a;
}
__device__ __forceinline__ void cp16(uint32_t dst, const void* src) {
    asm volatile("cp.async.cg.shared.global [%0], [%1], 16;" :: "r"(dst), "l"(src));
}
__device__ __forceinline__ void ldm_x4(uint32_t* r, uint32_t addr) {
    asm volatile("ldmatrix.sync.aligned.m8n8.x4.shared.b16 {%0,%1,%2,%3}, [%4];"
                 : "=r"(r[0]), "=r"(r[1]), "=r"(r[2]), "=r"(r[3]) : "r"(addr));
}
__device__ __forceinline__ void mma16816(float* d, const uint32_t* a, const uint32_t* b) {
    asm volatile("mma.sync.aligned.m16n8k16.row.col.f32.bf16.bf16.f32 "
                 "{%0,%1,%2,%3}, {%4,%5,%6,%7}, {%8,%9}, {%0,%1,%2,%3};"
                 : "+f"(d[0]), "+f"(d[1]), "+f"(d[2]), "+f"(d[3])
                 : "r"(a[0]), "r"(a[1]), "r"(a[2]), "r"(a[3]), "r"(b[0]), "r"(b[1]));
}

// ---------------- copy x -> out ----------------
__global__ void copy_f32(const float* __restrict__ in, float* __restrict__ out, int n) {
    int i = blockIdx.x * blockDim.x + threadIdx.x;
    if (i < n) out[i] = in[i];
}

// ---------------- weight conversion ----------------
__global__ void cvt_bf16_k(const float* __restrict__ s, __nv_bfloat16* __restrict__ d, int n) {
    int i = blockIdx.x * blockDim.x + threadIdx.x;
    if (i < n) d[i] = __float2bfloat16(s[i]);
}
__global__ void cvt_xproj_k(const float* __restrict__ s, __nv_bfloat16* __restrict__ d) {
    int i = blockIdx.x * blockDim.x + threadIdx.x;
    if (i >= NL * 64 * DI) return;
    int layer = i / (64 * DI);
    int rem   = i - layer * 64 * DI;
    int row   = rem / DI;
    int col   = rem - row * DI;
    float v = (row < 48) ? s[((size_t)layer * 48 + row) * DI + col] : 0.f;
    d[i] = __float2bfloat16(v);
}

// ---------------- layernorm -> bf16 ----------------
__global__ void layernorm_k(const float* __restrict__ h, const float* __restrict__ g,
                            const float* __restrict__ b, __nv_bfloat16* __restrict__ o) {
    __shared__ float red[16];
    __shared__ float smu, srv;
    int row = blockIdx.x;
    int tid = threadIdx.x;
    float v = h[(size_t)row * DM + tid];
    float s = v, s2 = v * v;
    #pragma unroll
    for (int off = 16; off; off >>= 1) {
        s  += __shfl_xor_sync(0xffffffffu, s,  off);
        s2 += __shfl_xor_sync(0xffffffffu, s2, off);
    }
    int w = tid >> 5;
    if ((tid & 31) == 0) { red[w] = s; red[8 + w] = s2; }
    __syncthreads();
    if (tid == 0) {
        float S = 0.f, S2 = 0.f;
        #pragma unroll
        for (int i = 0; i < 8; i++) { S += red[i]; S2 += red[8 + i]; }
        float mu = S * (1.f / DM);
        smu = mu;
        srv = rsqrtf(S2 * (1.f / DM) - mu * mu + 1e-5f);
    }
    __syncthreads();
    o[(size_t)row * DM + tid] = __float2bfloat16((v - smu) * srv * g[tid] + b[tid]);
}

// ---------------- bf16 tensor-core GEMM via mma.sync ----------------
// C[M,N] = A[M,K] @ W[N,K]^T.  A,W bf16 K-major; C fp32.
// Tiles: 128 x BN x 64, double-buffered cp.async, SW128 swizzle.
// EPI 0: store; EPI 1: store if n < nvalid; EPI 2: accumulate.
template <int BN, int EPI>
__global__ __launch_bounds__(256)
void mma_gemm(const __nv_bfloat16* __restrict__ A, const __nv_bfloat16* __restrict__ W,
              float* __restrict__ C, int K, int ldc, int nvalid) {
    constexpr int NF = BN / 16;              // n8-frag count per warp = 2*NF/2
    constexpr int ABYTES = 128 * 128;
    constexpr int BBYTES = BN * 128;
    constexpr int BUF = ABYTES + BBYTES;

    extern __shared__ __align__(1024) char smem[];
    const uint32_t sbase = smem_u32(smem);

    const int tid = threadIdx.x;
    const int wid = tid >> 5, lane = tid & 31;
    const int wm = (wid & 3) * 32;           // warp m offset in tile
    const int wn = (wid >> 2) * (BN / 2);    // warp n offset in tile
    const int m0 = blockIdx.x * 128;
    const int n0 = blockIdx.y * BN;

    float acc[2][NF][4];
    #pragma unroll
    for (int i = 0; i < 2; i++)
        #pragma unroll
        for (int j = 0; j < NF; j++)
            #pragma unroll
            for (int q = 0; q < 4; q++) acc[i][j][q] = 0.f;

    const int nk = K >> 6;

    // ---- prologue: load chunk 0 into buf 0 ----
    {
        const uint32_t sb = sbase;
        #pragma unroll
        for (int i = 0; i < 4; i++) {
            int idx = tid + i * 256;
            int r = idx >> 3, c = idx & 7;
            cp16(sb + SW128(r * 128 + c * 16), A + (size_t)(m0 + r) * K + c * 8);
        }
        #pragma unroll
        for (int i = 0; i < BN * 8 / 256; i++) {
            int idx = tid + i * 256;
            int r = idx >> 3, c = idx & 7;
            cp16(sb + ABYTES + SW128(r * 128 + c * 16), W + (size_t)(n0 + r) * K + c * 8);
        }
        asm volatile("cp.async.commit_group;");
    }

    for (int ic = 0; ic < nk; ic++) {
        if (ic + 1 < nk) {
            const int kc = (ic + 1) << 6;
            const uint32_t sb = sbase + ((ic + 1) & 1) * BUF;
            #pragma unroll
            for (int i = 0; i < 4; i++) {
                int idx = tid + i * 256;
                int r = idx >> 3, c = idx & 7;
                cp16(sb + SW128(r * 128 + c * 16), A + (size_t)(m0 + r) * K + kc + c * 8);
            }
            #pragma unroll
            for (int i = 0; i < BN * 8 / 256; i++) {
                int idx = tid + i * 256;
                int r = idx >> 3, c = idx & 7;
                cp16(sb + ABYTES + SW128(r * 128 + c * 16), W + (size_t)(n0 + r) * K + kc + c * 8);
            }
            asm volatile("cp.async.commit_group;");
            asm volatile("cp.async.wait_group 1;");
        } else {
            asm volatile("cp.async.wait_group 0;");
        }
        __syncthreads();

        const uint32_t abase = sbase + (ic & 1) * BUF;
        const uint32_t bbase = abase + ABYTES;
        #pragma unroll
        for (int ks = 0; ks < 4; ks++) {
            uint32_t afr[2][4];
            #pragma unroll
            for (int mt = 0; mt < 2; mt++) {
                int row = wm + mt * 16 + (lane & 15);
                int hk  = lane >> 4;                    // 0/1 -> k, k+8
                ldm_x4(afr[mt], abase + SW128(row * 128 + ks * 32 + hk * 16));
            }
            #pragma unroll
            for (int nf2 = 0; nf2 < NF / 2; nf2++) {
                uint32_t bfr[4];
                int nrow = wn + nf2 * 16 + (lane & 7) + ((lane >> 4) << 3);
                int hk   = (lane >> 3) & 1;
                ldm_x4(bfr, bbase + SW128(nrow * 128 + ks * 32 + hk * 16));
                #pragma unroll
                for (int mt = 0; mt < 2; mt++) {
                    mma16816(acc[mt][2 * nf2],     afr[mt], bfr);
                    mma16816(acc[mt][2 * nf2 + 1], afr[mt], bfr + 2);
                }
            }
        }
        __syncthreads();
    }

    // ---- epilogue ----
    #pragma unroll
    for (int mt = 0; mt < 2; mt++) {
        int r0 = m0 + wm + mt * 16 + (lane >> 2);
        #pragma unroll
        for (int nf = 0; nf < NF; nf++) {
            int cl = n0 + wn + nf * 8 + (lane & 3) * 2;
            float* p0 = C + (size_t)r0 * ldc + cl;
            float* p1 = p0 + (size_t)8 * ldc;
            if (EPI == 1 && cl >= nvalid) continue;
            if (EPI == 2) {
                float2 t0 = *(float2*)p0;
                float2 t1 = *(float2*)p1;
                t0.x += acc[mt][nf][0]; t0.y += acc[mt][nf][1];
                t1.x += acc[mt][nf][2]; t1.y += acc[mt][nf][3];
                *(float2*)p0 = t0;
                *(float2*)p1 = t1;
            } else {
                *(float2*)p0 = make_float2(acc[mt][nf][0], acc[mt][nf][1]);
                *(float2*)p1 = make_float2(acc[mt][nf][2], acc[mt][nf][3]);
            }
        }
    }
}

// ---------------- fp32 SGEMM (dt projection, K=16) + softplus ----------------
__global__ __launch_bounds__(256)
void sgemm_dt(const float* __restrict__ A, int lda,
              const float* __restrict__ W,
              const float* __restrict__ bias,
              float* __restrict__ C, int ldc,
              int M, int N, int K) {
    const int BM = 64, BN = 64, BK = 16;
    __shared__ float As[BK][BM + 4];
    __shared__ float Bs[BK][BN + 4];
    int tid = threadIdx.x;
    int m0 = blockIdx.x * BM;
    int n0 = blockIdx.y * BN;
    int tx = tid & 15, ty = tid >> 4;
    float acc[4][4] = {};
    int l_r = tid >> 2;
    int l_k = (tid & 3) * 4;

    for (int k0 = 0; k0 < K; k0 += BK) {
        float4 av = *(const float4*)(A + (size_t)(m0 + l_r) * lda + k0 + l_k);
        As[l_k + 0][l_r] = av.x; As[l_k + 1][l_r] = av.y;
        As[l_k + 2][l_r] = av.z; As[l_k + 3][l_r] = av.w;
        float4 bv = *(const float4*)(W + (size_t)(n0 + l_r) * K + k0 + l_k);
        Bs[l_k + 0][l_r] = bv.x; Bs[l_k + 1][l_r] = bv.y;
        Bs[l_k + 2][l_r] = bv.z; Bs[l_k + 3][l_r] = bv.w;
        __syncthreads();
        #pragma unroll
        for (int k = 0; k < BK; ++k) {
            float4 ar = *(const float4*)&As[k][ty * 4];
            float4 br = *(const float4*)&Bs[k][tx * 4];
            float a[4] = {ar.x, ar.y, ar.z, ar.w};
            float b[4] = {br.x, br.y, br.z, br.w};
            #pragma unroll
            for (int i = 0; i < 4; i++)
                #pragma unroll
                for (int j = 0; j < 4; j++)
                    acc[i][j] += a[i] * b[j];
        }
        __syncthreads();
    }
    #pragma unroll
    for (int i = 0; i < 4; i++) {
        int m = m0 + ty * 4 + i;
        #pragma unroll
        for (int j = 0; j < 4; j++) {
            int n = n0 + tx * 4 + j;
            float v = acc[i][j] + bias[n];
            v = fmaxf(v, 0.f) + log1pf(__expf(-fabsf(v)));
            C[(size_t)m * ldc + n] = v;
        }
    }
}

// ---------------- causal depthwise conv1d + SiLU ----------------
__global__ void conv_silu_k(const float* __restrict__ xz, const float* __restrict__ w,
                            const float* __restrict__ bias, float* __restrict__ u,
                            __nv_bfloat16* __restrict__ ub) {
    int idx = blockIdx.x * blockDim.x + threadIdx.x;
    if (idx >= BL * DI) return;
    int d   = idx & (DI - 1);
    int row = idx >> 9;
    int t   = row & (SEQ_L - 1);
    float acc = bias[d];
    #pragma unroll
    for (int k = 0; k < DC; ++k) {
        int tt = t - (DC - 1) + k;
        if (tt >= 0) acc += w[d * DC + k] * xz[(size_t)(row - (DC - 1) + k) * (2 * DI) + d];
    }
    float v = acc / (1.f + __expf(-acc));
    u[idx] = v;
    ub[idx] = __float2bfloat16(v);
}

// ---------------- selective scan (fused gating) ----------------
#define TCH 64
__global__ __launch_bounds__(256)
void scan_k(const float* __restrict__ dt, const float* __restrict__ u,
            const float* __restrict__ dbc, const float* __restrict__ xz,
            const float* __restrict__ A_log, const float* __restrict__ Dp,
            __nv_bfloat16* __restrict__ y) {
    __shared__ float s_dt[TCH][16];
    __shared__ float s_u [TCH][16];
    __shared__ float s_b [TCH][16];
    __shared__ float s_c [TCH][16];
    __shared__ float s_z [TCH][16];

    int b  = blockIdx.x >> 5;
    int d0 = (blockIdx.x & 31) * 16;
    int c  = threadIdx.x >> 4;
    int s  = threadIdx.x & 15;
    int d  = d0 + c;

    float Acoef = -__expf(A_log[d * DS + s]);
    float Dv = Dp[d];
    float h = 0.f;

    size_t base = (size_t)b * SEQ_L;
    for (int t0 = 0; t0 < SEQ_L; t0 += TCH) {
        __syncthreads();
        for (int j = threadIdx.x; j < TCH * 16; j += 256) {
            int r = j >> 4, cc = j & 15;
            size_t row = base + t0 + r;
            s_dt[r][cc] = dt[row * DI + d0 + cc];
            s_u [r][cc] = u [row * DI + d0 + cc];
            s_z [r][cc] = xz[row * (2 * DI) + DI + d0 + cc];
            s_b [r][cc] = dbc[row * 48 + 16 + cc];
            s_c [r][cc] = dbc[row * 48 + 32 + cc];
        }
        __syncthreads();
        #pragma unroll 4
        for (int tt = 0; tt < TCH; ++tt) {
            float dtv = s_dt[tt][c];
            float uv  = s_u[tt][c];
            float dA  = __expf(dtv * Acoef);
            h = h * dA + dtv * uv * s_b[tt][s];
            float yp = h * s_c[tt][s];
            yp += __shfl_xor_sync(0xffffffffu, yp, 8);
            yp += __shfl_xor_sync(0xffffffffu, yp, 4);
            yp += __shfl_xor_sync(0xffffffffu, yp, 2);
            yp += __shfl_xor_sync(0xffffffffu, yp, 1);
            if (s == 0) {
                float zv = s_z[tt][c];
                float sz = zv / (1.f + __expf(-zv));
                y[(base + t0 + tt) * DI + d] = __float2bfloat16((yp + uv * Dv) * sz);
            }
        }
    }
}

// ---------------- host launcher ----------------
extern "C" void kernel_launch(void* const* d_in, const int* in_sizes, int n_in,
                              void* d_out, int out_size) {
    const float* x        = (const float*)d_in[0];
    const float* ln_g     = (const float*)d_in[1];
    const float* ln_b     = (const float*)d_in[2];
    const float* in_w     = (const float*)d_in[3];
    const float* conv_w   = (const float*)d_in[4];
    const float* conv_b   = (const float*)d_in[5];
    const float* xproj_w  = (const float*)d_in[6];
    const float* dtproj_w = (const float*)d_in[7];
    const float* dtproj_b = (const float*)d_in[8];
    const float* A_log    = (const float*)d_in[9];
    const float* Dp       = (const float*)d_in[10];
    const float* out_w    = (const float*)d_in[11];
    float* out = (float*)d_out;

    __nv_bfloat16 *hn_b, *u_b, *y_b, *win_b, *wx_b, *wout_b;
    float *xz, *u, *dbc, *dt;
    cudaGetSymbolAddress((void**)&hn_b,  g_hn_b);
    cudaGetSymbolAddress((void**)&xz,    g_xz);
    cudaGetSymbolAddress((void**)&u,     g_u);
    cudaGetSymbolAddress((void**)&u_b,   g_u_b);
    cudaGetSymbolAddress((void**)&dbc,   g_dbc);
    cudaGetSymbolAddress((void**)&dt,    g_dt);
    cudaGetSymbolAddress((void**)&y_b,   g_y_b);
    cudaGetSymbolAddress((void**)&win_b, g_win_b);
    cudaGetSymbolAddress((void**)&wx_b,  g_wx_b);
    cudaGetSymbolAddress((void**)&wout_b,g_wout_b);

    // dynamic smem caps (idempotent; host-side, graph-capture safe)
    const int SM128 = 2 * (128 + 128) * 128;   // 65536
    const int SM64  = 2 * (128 + 64) * 128;    // 49152
    cudaFuncSetAttribute(mma_gemm<128, 0>, cudaFuncAttributeMaxDynamicSharedMemorySize, SM128);
    cudaFuncSetAttribute(mma_gemm<64, 1>,  cudaFuncAttributeMaxDynamicSharedMemorySize, SM64);
    cudaFuncSetAttribute(mma_gemm<128, 2>, cudaFuncAttributeMaxDynamicSharedMemorySize, SM128);

    // weight conversion (deterministic each launch)
    {
        int n1 = NL * 2 * DI * DM;
        cvt_bf16_k<<<(n1 + 255) / 256, 256>>>(in_w, win_b, n1);
        int n2 = NL * DM * DI;
        cvt_bf16_k<<<(n2 + 255) / 256, 256>>>(out_w, wout_b, n2);
        int n3 = NL * 64 * DI;
        cvt_xproj_k<<<(n3 + 255) / 256, 256>>>(xproj_w, wx_b);
    }

    const int n_out = BL * DM;
    copy_f32<<<(n_out + 255) / 256, 256>>>(x, out, n_out);

    for (int i = 0; i < NL; ++i) {
        // 1. layernorm -> bf16
        layernorm_k<<<BL, 256>>>(out, ln_g, ln_b, hn_b);
        // 2. in_proj: xz[BL,1024] = hn @ in_w^T (K=256)
        mma_gemm<128, 0><<<dim3(BL / 128, 8), 256, SM128>>>(
            hn_b, win_b + (size_t)i * 2 * DI * DM, xz, DM, 2 * DI, 2 * DI);
        // 3. conv + silu
        conv_silu_k<<<(BL * DI + 255) / 256, 256>>>(
            xz, conv_w + (size_t)i * DI * DC, conv_b + (size_t)i * DI, u, u_b);
        // 4. x_proj: dbc[BL,48] = u @ xproj^T (K=512, N padded to 64)
        mma_gemm<64, 1><<<dim3(BL / 128, 1), 256, SM64>>>(
            u_b, wx_b + (size_t)i * 64 * DI, dbc, DI, 48, 48);
        // 5. dt projection (fp32, K=16) + softplus
        sgemm_dt<<<dim3(BL / 64, DI / 64), 256>>>(
            dbc, 48, dtproj_w + (size_t)i * DI * DTR, dtproj_b + (size_t)i * DI,
            dt, DI, BL, DI, DTR);
        // 6. selective scan + gating -> y (bf16)
        scan_k<<<B_SZ * 32, 256>>>(dt, u, dbc, xz,
                                   A_log + (size_t)i * DI * DS, Dp + (size_t)i * DI, y_b);
        // 7. out_proj with residual accumulate (K=512)
        mma_gemm<128, 2><<<dim3(BL / 128, 2), 256, SM128>>>(
            y_b, wout_b + (size_t)i * DM * DI, out, DI, DM, DM);
    }
}